// round 7
// baseline (speedup 1.0000x reference)
#include <cuda_runtime.h>
#include <cuda_bf16.h>
#include <cstddef>

#define EMB 256
#define HID 128
#define N_REL 10
#define LDA 136   // padded bf16 row stride (272B: rows step 4 banks -> LDSM conflict-free)

// ---------------- global scratch ----------------
__device__ float g_P[(size_t)100000 * 256];   // per-node projections
__device__ float g_M[N_REL * 128 * 4];        // folded K/Q table m[r][k][h]
__device__ float g_C[N_REL * 4];              // folded bias c[r][h]
// Pre-packed transposed weights, hi/lo bf16, padded row-major [n][LDA]
__device__ __align__(16) __nv_bfloat16 g_BvH[128 * LDA];
__device__ __align__(16) __nv_bfloat16 g_BvL[128 * LDA];
__device__ __align__(16) __nv_bfloat16 g_BoH[128 * LDA];
__device__ __align__(16) __nv_bfloat16 g_BoL[128 * LDA];
__device__ __align__(16) __nv_bfloat16 g_BeH[4 * 128 * LDA];  // [cb*2+chunk][n][LDA]
__device__ __align__(16) __nv_bfloat16 g_BeL[4 * 128 * LDA];

// ---------------- helpers ----------------
__device__ __forceinline__ void split2(float x0, float x1, unsigned& hi, unsigned& lo) {
    __nv_bfloat162 h = __floats2bfloat162_rn(x0, x1);
    float r0 = x0 - __bfloat162float(h.x);
    float r1 = x1 - __bfloat162float(h.y);
    __nv_bfloat162 l = __floats2bfloat162_rn(r0, r1);
    hi = *(unsigned*)&h;
    lo = *(unsigned*)&l;
}

__device__ __forceinline__ void mma16816(float* d, const unsigned* a, unsigned b0, unsigned b1) {
    asm volatile(
        "mma.sync.aligned.m16n8k16.row.col.f32.bf16.bf16.f32 "
        "{%0,%1,%2,%3}, {%4,%5,%6,%7}, {%8,%9}, {%0,%1,%2,%3};"
        : "+f"(d[0]), "+f"(d[1]), "+f"(d[2]), "+f"(d[3])
        : "r"(a[0]), "r"(a[1]), "r"(a[2]), "r"(a[3]), "r"(b0), "r"(b1));
}

__device__ __forceinline__ void ldsm4(unsigned r[4], unsigned addr) {
    asm volatile("ldmatrix.sync.aligned.m8n8.x4.shared.b16 {%0,%1,%2,%3}, [%4];"
        : "=r"(r[0]), "=r"(r[1]), "=r"(r[2]), "=r"(r[3]) : "r"(addr));
}
__device__ __forceinline__ unsigned scvta(const void* p) {
    return (unsigned)__cvta_generic_to_shared(p);
}

// Per-lane ldmatrix source coordinates.
// A x4: matrices (m0-7,k0-7),(m8-15,k0-7),(m0-7,k8-15),(m8-15,k8-15)
//   lane l -> row (l&7) + ((l>>3)&1)*8, col (l>>4)*8
// B x4: matrices (n0-7,k0-7),(n0-7,k8-15),(n8-15,k0-7),(n8-15,k8-15)
//   lane l -> row (l&7) + (l>>4)*8, col ((l>>3)&1)*8
// regs: r0=b0(n-tile even), r1=b1(even), r2=b0(odd), r3=b1(odd)

// D += A1@B^T + A2@B^T (two A tiles vs one resident B tile), ldmatrix frags
__device__ __forceinline__ void gemm_2t(
    const __nv_bfloat16* A1, const __nv_bfloat16* A2, const __nv_bfloat16* B,
    int wm, int wn, int lane, float d[2][8][4])
{
    int ar = (lane & 7) + ((lane >> 3) & 1) * 8;
    int ac = (lane >> 4) * 8;
    int br = (lane & 7) + (lane >> 4) * 8;
    int bc = ((lane >> 3) & 1) * 8;
    unsigned aA1[2], aA2[2], aB[4];
#pragma unroll
    for (int t = 0; t < 2; t++) {
        aA1[t] = scvta(A1 + (wm * 32 + t * 16 + ar) * LDA + ac);
        aA2[t] = scvta(A2 + (wm * 32 + t * 16 + ar) * LDA + ac);
    }
#pragma unroll
    for (int jp = 0; jp < 4; jp++)
        aB[jp] = scvta(B + (wn * 64 + jp * 16 + br) * LDA + bc);

#pragma unroll
    for (int ks = 0; ks < 8; ks++) {
        unsigned koffb = ks * 32;   // 16 bf16
        unsigned a1[2][4], a2[2][4];
#pragma unroll
        for (int t = 0; t < 2; t++) {
            ldsm4(a1[t], aA1[t] + koffb);
            ldsm4(a2[t], aA2[t] + koffb);
        }
#pragma unroll
        for (int jp = 0; jp < 4; jp++) {
            unsigned bb[4];
            ldsm4(bb, aB[jp] + koffb);
#pragma unroll
            for (int t = 0; t < 2; t++) {
                mma16816(d[t][jp * 2 + 0], a1[t], bb[0], bb[1]);
                mma16816(d[t][jp * 2 + 0], a2[t], bb[0], bb[1]);
                mma16816(d[t][jp * 2 + 1], a1[t], bb[2], bb[3]);
                mma16816(d[t][jp * 2 + 1], a2[t], bb[2], bb[3]);
            }
        }
    }
}

// D += A1@B^T
__device__ __forceinline__ void gemm_1t(
    const __nv_bfloat16* A1, const __nv_bfloat16* B,
    int wm, int wn, int lane, float d[2][8][4])
{
    int ar = (lane & 7) + ((lane >> 3) & 1) * 8;
    int ac = (lane >> 4) * 8;
    int br = (lane & 7) + (lane >> 4) * 8;
    int bc = ((lane >> 3) & 1) * 8;
    unsigned aA1[2], aB[4];
#pragma unroll
    for (int t = 0; t < 2; t++)
        aA1[t] = scvta(A1 + (wm * 32 + t * 16 + ar) * LDA + ac);
#pragma unroll
    for (int jp = 0; jp < 4; jp++)
        aB[jp] = scvta(B + (wn * 64 + jp * 16 + br) * LDA + bc);

#pragma unroll
    for (int ks = 0; ks < 8; ks++) {
        unsigned koffb = ks * 32;
        unsigned a1[2][4];
#pragma unroll
        for (int t = 0; t < 2; t++) ldsm4(a1[t], aA1[t] + koffb);
#pragma unroll
        for (int jp = 0; jp < 4; jp++) {
            unsigned bb[4];
            ldsm4(bb, aB[jp] + koffb);
#pragma unroll
            for (int t = 0; t < 2; t++) {
                mma16816(d[t][jp * 2 + 0], a1[t], bb[0], bb[1]);
                mma16816(d[t][jp * 2 + 1], a1[t], bb[2], bb[3]);
            }
        }
    }
}

__device__ __forceinline__ void copyB(const __nv_bfloat16* src, __nv_bfloat16* dst, int tid) {
    const float4* s = (const float4*)src;
    float4* d = (float4*)dst;
    for (int u = tid; u < 2176; u += 256) d[u] = s[u];
}

// ---------------------------------------------------------------------------
// prep: fold Q-path through W_k (m-table)
// ---------------------------------------------------------------------------
__global__ void prep_kernel(const float* __restrict__ rel_emb,
                            const float* __restrict__ W_q,
                            const float* __restrict__ b_q,
                            const float* __restrict__ W_k,
                            const float* __restrict__ b_k) {
    __shared__ float qh[128];
    int r = blockIdx.x;
    int c = threadIdx.x;
    float s = b_q[c];
#pragma unroll 16
    for (int t = 0; t < 64; t++) s = fmaf(rel_emb[r * 64 + t], W_q[t * 128 + c], s);
    qh[c] = s;
    __syncthreads();
    int k = threadIdx.x;
    float m[4] = {0.f, 0.f, 0.f, 0.f};
#pragma unroll 8
    for (int d = 0; d < 32; d++)
#pragma unroll
        for (int h = 0; h < 4; h++)
            m[h] = fmaf(W_k[k * 128 + h * 32 + d], qh[h * 32 + d], m[h]);
    float4 m4 = {m[0], m[1], m[2], m[3]};
    *(float4*)(g_M + r * 512 + k * 4) = m4;
    if (k < 4) {
        float cc = 0.f;
#pragma unroll 8
        for (int d = 0; d < 32; d++) cc = fmaf(b_k[k * 32 + d], qh[k * 32 + d], cc);
        g_C[r * 4 + k] = cc;
    }
}

// ---------------------------------------------------------------------------
// packb: transposed weights -> padded hi/lo bf16 images
// ---------------------------------------------------------------------------
__global__ void packb_kernel(const float* __restrict__ Wv,
                             const float* __restrict__ Wo1,
                             const float* __restrict__ Wedge) {
    int idx = blockIdx.x * 256 + threadIdx.x;
    if (idx < 16384) {
        int n = idx & 127, k = idx >> 7;
        float x = Wv[k * 128 + n];
        __nv_bfloat16 h = __float2bfloat16(x);
        g_BvH[n * LDA + k] = h;
        g_BvL[n * LDA + k] = __float2bfloat16(x - __bfloat162float(h));
    } else if (idx < 32768) {
        int t = idx - 16384;
        int n = t & 127, k = t >> 7;
        float x = Wo1[k * 128 + n];
        __nv_bfloat16 h = __float2bfloat16(x);
        g_BoH[n * LDA + k] = h;
        g_BoL[n * LDA + k] = __float2bfloat16(x - __bfloat162float(h));
    } else if (idx < 98304) {
        int t = idx - 32768;
        int cb = t >> 15;
        int r = t & 32767;
        int k = r >> 7;
        int n = r & 127;
        int chunk = k >> 7, kl = k & 127;
        size_t o = (size_t)((cb * 2 + chunk) * 128 + n) * LDA + kl;
        float x = Wedge[(size_t)(cb * 256 + k) * 128 + n];
        __nv_bfloat16 h = __float2bfloat16(x);
        g_BeH[o] = h;
        g_BeL[o] = __float2bfloat16(x - __bfloat162float(h));
    }
}

// ---------------------------------------------------------------------------
// nodeproj: single-B-buffer, smem 104448B -> 2 blocks/SM
// ---------------------------------------------------------------------------
__global__ __launch_bounds__(256, 2) void nodeproj_kernel(const float* __restrict__ emb,
                                                          int n_nodes) {
    extern __shared__ __align__(16) char sm[];
    __nv_bfloat16* AH = (__nv_bfloat16*)sm;
    __nv_bfloat16* AL = AH + 128 * LDA;
    __nv_bfloat16* B  = AL + 128 * LDA;

    int tid = threadIdx.x;
    int lane = tid & 31, wid = tid >> 5;
    int g = lane >> 2, tk = lane & 3;
    int wm = wid >> 1, wn = wid & 1;
    int n0 = blockIdx.x * 128;
    int cb = blockIdx.y;

    float d[2][8][4];
#pragma unroll
    for (int t = 0; t < 2; t++)
#pragma unroll
        for (int j = 0; j < 8; j++)
#pragma unroll
            for (int c = 0; c < 4; c++) d[t][j][c] = 0.f;

    for (int chunk = 0; chunk < 2; chunk++) {
        __syncthreads();   // previous gemm done reading A/B
        // build A chunk
        {
            int row = tid >> 1, q = tid & 1;
            int n = n0 + row; if (n >= n_nodes) n = n_nodes - 1;
            const float4* np = (const float4*)(emb + (size_t)n * EMB + chunk * 128 + q * 64);
#pragma unroll
            for (int u = 0; u < 16; u++) {
                float4 v = np[u];
                unsigned h0, l0, h1, l1;
                split2(v.x, v.y, h0, l0);
                split2(v.z, v.w, h1, l1);
                int c = q * 64 + u * 4;
                *(unsigned*)(AH + row * LDA + c) = h0;
                *(unsigned*)(AH + row * LDA + c + 2) = h1;
                *(unsigned*)(AL + row * LDA + c) = l0;
                *(unsigned*)(AL + row * LDA + c + 2) = l1;
            }
        }
        copyB(g_BeH + (size_t)(cb * 2 + chunk) * 128 * LDA, B, tid);
        __syncthreads();
        gemm_2t(AH, AL, B, wm, wn, lane, d);        // Ah*Bh + Al*Bh
        __syncthreads();
        copyB(g_BeL + (size_t)(cb * 2 + chunk) * 128 * LDA, B, tid);
        __syncthreads();
        gemm_1t(AH, B, wm, wn, lane, d);            // Ah*Bl
    }
    // store D -> g_P
#pragma unroll
    for (int t = 0; t < 2; t++) {
        int lr = wm * 32 + t * 16 + g;
#pragma unroll
        for (int j = 0; j < 8; j++) {
            int col = cb * 128 + wn * 64 + j * 8 + 2 * tk;
            int n = n0 + lr;
            if (n < n_nodes) {
                float2 v = {d[t][j][0], d[t][j][1]};
                *(float2*)(g_P + (size_t)n * 256 + col) = v;
            }
            int n2 = n0 + lr + 8;
            if (n2 < n_nodes) {
                float2 v = {d[t][j][2], d[t][j][3]};
                *(float2*)(g_P + (size_t)n2 * 256 + col) = v;
            }
        }
    }
}

// ---------------------------------------------------------------------------
// edge kernel: single-B-buffer, smem 110592B -> 2 blocks/SM
// ---------------------------------------------------------------------------
__global__ __launch_bounds__(256, 2) void edge_kernel(
    const int* __restrict__ edge_index, const int* __restrict__ rel_type,
    const float* __restrict__ b_edge,
    const float* __restrict__ b_v, const float* __restrict__ b_o1,
    const float* __restrict__ W_o2, const float* __restrict__ b_o2,
    float* __restrict__ out, int E) {
    extern __shared__ __align__(16) char sm[];
    __nv_bfloat16* AH = (__nv_bfloat16*)sm;
    __nv_bfloat16* AL = AH + 128 * LDA;
    __nv_bfloat16* B  = AL + 128 * LDA;
    float* sSc = (float*)(sm + 104448);
    int* sSrc  = (int*)(sm + 106496);
    int* sTgt  = (int*)(sm + 107008);
    int* sRel  = (int*)(sm + 107520);
    float* sBv = (float*)(sm + 108032);
    float* sBo = (float*)(sm + 108544);
    float* sW2 = (float*)(sm + 109056);
    float* sOut = (float*)(sm + 109568);

    int tid = threadIdx.x;
    int lane = tid & 31, wid = tid >> 5;
    int g = lane >> 2, tk = lane & 3;
    int wm = wid >> 1, wn = wid & 1;
    int e0 = blockIdx.x * 128;

    // ---- stage indices/biases + B <- BvH ----
    if (tid < 128) {
        int e = e0 + tid;
        int eg = e < E ? e : E - 1;
        sSrc[tid] = edge_index[eg];
        sTgt[tid] = edge_index[E + eg];
        sRel[tid] = rel_type[eg];
        sBv[tid] = b_v[tid];
        sBo[tid] = b_o1[tid];
        sW2[tid] = W_o2[tid];
    }
    copyB(g_BvH, B, tid);
    __syncthreads();

    // ---- build hs = relu(P[src][0:128] + P[tgt][128:256] + b_edge), split ----
    {
        int row = tid >> 1, q = tid & 1;
        const float4* ps = (const float4*)(g_P + (size_t)sSrc[row] * 256 + q * 64);
        const float4* pt = (const float4*)(g_P + (size_t)sTgt[row] * 256 + 128 + q * 64);
        const float4* bb = (const float4*)(b_edge + q * 64);
#pragma unroll
        for (int u = 0; u < 16; u++) {
            float4 a = ps[u], b = pt[u], c = bb[u];
            float x0 = fmaxf(a.x + b.x + c.x, 0.f);
            float x1 = fmaxf(a.y + b.y + c.y, 0.f);
            float x2 = fmaxf(a.z + b.z + c.z, 0.f);
            float x3 = fmaxf(a.w + b.w + c.w, 0.f);
            unsigned h0, l0, h1, l1;
            split2(x0, x1, h0, l0);
            split2(x2, x3, h1, l1);
            int cc = q * 64 + u * 4;
            *(unsigned*)(AH + row * LDA + cc) = h0;
            *(unsigned*)(AH + row * LDA + cc + 2) = h1;
            *(unsigned*)(AL + row * LDA + cc) = l0;
            *(unsigned*)(AL + row * LDA + cc + 2) = l1;
        }
    }
    __syncthreads();

    // ---- scores: sSc[e][h] = (hs[e].m[rel,h] + c[rel,h]) / sqrt(32), m via __ldg ----
    {
        int tx = tid & 15, ty = tid >> 4;
#pragma unroll
        for (int i = 0; i < 8; i++) {
            int e = ty * 8 + i;
            int r = sRel[e];
            const float4* gm = (const float4*)(g_M + r * 512);
            float p[4] = {0.f, 0.f, 0.f, 0.f};
#pragma unroll
            for (int j = 0; j < 4; j++) {
                int k = j * 32 + 2 * tx;
                float2 xh = __bfloat1622float2(*(const __nv_bfloat162*)(AH + e * LDA + k));
                float2 xl = __bfloat1622float2(*(const __nv_bfloat162*)(AL + e * LDA + k));
                float h0 = xh.x + xl.x, h1 = xh.y + xl.y;
                float4 m0 = __ldg(gm + k);
                float4 m1 = __ldg(gm + k + 1);
                p[0] += h0 * m0.x + h1 * m1.x;
                p[1] += h0 * m0.y + h1 * m1.y;
                p[2] += h0 * m0.z + h1 * m1.z;
                p[3] += h0 * m0.w + h1 * m1.w;
            }
#pragma unroll
            for (int m = 1; m < 16; m <<= 1)
#pragma unroll
                for (int j = 0; j < 4; j++) p[j] += __shfl_xor_sync(0xffffffffu, p[j], m);
            if (tx == 0) {
                float c0 = __ldg(g_C + r * 4 + 0), c1 = __ldg(g_C + r * 4 + 1);
                float c2 = __ldg(g_C + r * 4 + 2), c3 = __ldg(g_C + r * 4 + 3);
                sSc[e * 4 + 0] = (p[0] + c0) * 0.17677669529663687f;
                sSc[e * 4 + 1] = (p[1] + c1) * 0.17677669529663687f;
                sSc[e * 4 + 2] = (p[2] + c2) * 0.17677669529663687f;
                sSc[e * 4 + 3] = (p[3] + c3) * 0.17677669529663687f;
            }
        }
    }

    // ---- GEMM1: Ah*BvH + Al*BvH, then Ah*BvL ----
    float d[2][8][4];
#pragma unroll
    for (int t = 0; t < 2; t++)
#pragma unroll
        for (int j = 0; j < 8; j++)
#pragma unroll
            for (int c = 0; c < 4; c++) d[t][j][c] = 0.f;
    gemm_2t(AH, AL, B, wm, wn, lane, d);
    __syncthreads();
    copyB(g_BvL, B, tid);
    __syncthreads();
    gemm_1t(AH, B, wm, wn, lane, d);
    __syncthreads();

    // ---- epilogue1: softmax over heads, hs += attn*(V+b_v), re-split in place ----
#pragma unroll
    for (int t = 0; t < 2; t++) {
#pragma unroll
        for (int ch = 0; ch < 2; ch++) {
            int row = wm * 32 + t * 16 + g + ch * 8;
            float s0 = sSc[row * 4 + 0], s1 = sSc[row * 4 + 1];
            float s2 = sSc[row * 4 + 2], s3 = sSc[row * 4 + 3];
            float mx = fmaxf(fmaxf(s0, s1), fmaxf(s2, s3));
            float x0 = __expf(s0 - mx), x1 = __expf(s1 - mx);
            float x2 = __expf(s2 - mx), x3 = __expf(s3 - mx);
            float inv = 1.f / (x0 + x1 + x2 + x3);
            float at[4] = {x0 * inv, x1 * inv, x2 * inv, x3 * inv};
#pragma unroll
            for (int j = 0; j < 8; j++) {
#pragma unroll
                for (int cb2 = 0; cb2 < 2; cb2++) {
                    int col = wn * 64 + j * 8 + 2 * tk + cb2;
                    float v = d[t][j][ch * 2 + cb2] + sBv[col];
                    float x = __bfloat162float(AH[row * LDA + col]) +
                              __bfloat162float(AL[row * LDA + col]);
                    float nx = x + at[col >> 5] * v;
                    __nv_bfloat16 hh = __float2bfloat16(nx);
                    AH[row * LDA + col] = hh;
                    AL[row * LDA + col] = __float2bfloat16(nx - __bfloat162float(hh));
                }
            }
        }
    }
    copyB(g_BoH, B, tid);
    __syncthreads();

    // ---- GEMM2 ----
#pragma unroll
    for (int t = 0; t < 2; t++)
#pragma unroll
        for (int j = 0; j < 8; j++)
#pragma unroll
            for (int c = 0; c < 4; c++) d[t][j][c] = 0.f;
    gemm_2t(AH, AL, B, wm, wn, lane, d);
    __syncthreads();
    copyB(g_BoL, B, tid);
    __syncthreads();
    gemm_1t(AH, B, wm, wn, lane, d);

    // ---- epilogue2: relu(D2 + b_o1) . W_o2, quad reduce, combine ----
    float pacc[2][2] = {{0.f, 0.f}, {0.f, 0.f}};
#pragma unroll
    for (int t = 0; t < 2; t++)
#pragma unroll
        for (int ch = 0; ch < 2; ch++)
#pragma unroll
            for (int j = 0; j < 8; j++)
#pragma unroll
                for (int cb2 = 0; cb2 < 2; cb2++) {
                    int col = wn * 64 + j * 8 + 2 * tk + cb2;
                    float h = fmaxf(d[t][j][ch * 2 + cb2] + sBo[col], 0.f);
                    pacc[t][ch] = fmaf(h, sW2[col], pacc[t][ch]);
                }
#pragma unroll
    for (int m = 1; m <= 2; m <<= 1)
#pragma unroll
        for (int t = 0; t < 2; t++)
#pragma unroll
            for (int ch = 0; ch < 2; ch++)
                pacc[t][ch] += __shfl_xor_sync(0xffffffffu, pacc[t][ch], m);
    if (tk == 0) {
#pragma unroll
        for (int t = 0; t < 2; t++)
#pragma unroll
            for (int ch = 0; ch < 2; ch++) {
                int row = wm * 32 + t * 16 + g + ch * 8;
                sOut[wn * 128 + row] = pacc[t][ch];
            }
    }
    __syncthreads();
    if (tid < 128) {
        int e = e0 + tid;
        if (e < E) out[e] = sOut[tid] + sOut[128 + tid] + __ldg(b_o2);
    }
}

// ---------------------------------------------------------------------------
extern "C" void kernel_launch(void* const* d_in, const int* in_sizes, int n_in,
                              void* d_out, int out_size) {
    const float* node_emb = (const float*)d_in[0];
    const int*   edge_index = (const int*)d_in[1];
    const int*   rel_type = (const int*)d_in[2];
    const float* rel_emb = (const float*)d_in[3];
    const float* W_edge = (const float*)d_in[4];
    const float* b_edge = (const float*)d_in[5];
    const float* W_q = (const float*)d_in[6];
    const float* b_q = (const float*)d_in[7];
    const float* W_k = (const float*)d_in[8];
    const float* b_k = (const float*)d_in[9];
    const float* W_v = (const float*)d_in[10];
    const float* b_v = (const float*)d_in[11];
    const float* W_o1 = (const float*)d_in[12];
    const float* b_o1 = (const float*)d_in[13];
    const float* W_o2 = (const float*)d_in[14];
    const float* b_o2 = (const float*)d_in[15];
    float* out = (float*)d_out;

    int n_nodes = in_sizes[0] / EMB;   // 100000
    int E = in_sizes[2];               // 500000

    prep_kernel<<<N_REL, 128>>>(rel_emb, W_q, b_q, W_k, b_k);
    packb_kernel<<<384, 256>>>(W_v, W_o1, W_edge);

    const int SMEM_NP = 3 * 128 * LDA * 2;     // 104448
    cudaFuncSetAttribute(nodeproj_kernel, cudaFuncAttributeMaxDynamicSharedMemorySize, SMEM_NP);
    dim3 g2((n_nodes + 127) / 128, 2);
    nodeproj_kernel<<<g2, 256, SMEM_NP>>>(node_emb, n_nodes);

    const int SMEM_E = 110592;
    cudaFuncSetAttribute(edge_kernel, cudaFuncAttributeMaxDynamicSharedMemorySize, SMEM_E);
    edge_kernel<<<(E + 127) / 128, 256, SMEM_E>>>(
        edge_index, rel_type, b_edge, b_v, b_o1, W_o2, b_o2, out, E);
}

// round 8
// speedup vs baseline: 1.1839x; 1.1839x over previous
#include <cuda_runtime.h>
#include <cuda_bf16.h>
#include <cstddef>

#define EMB 256
#define HID 128
#define N_REL 10
#define LDA 136   // padded bf16 row stride (272B: rows step 4 banks -> LDSM conflict-free)

// ---------------- global scratch ----------------
__device__ float g_P[(size_t)100000 * 256];   // per-node projections
__device__ float g_M[N_REL * 128 * 4];        // folded K/Q table m[r][k][h]
__device__ float g_C[N_REL * 4];              // folded bias c[r][h]
__device__ __align__(16) __nv_bfloat16 g_BvH[128 * LDA];
__device__ __align__(16) __nv_bfloat16 g_BvL[128 * LDA];
__device__ __align__(16) __nv_bfloat16 g_BoH[128 * LDA];
__device__ __align__(16) __nv_bfloat16 g_BoL[128 * LDA];
__device__ __align__(16) __nv_bfloat16 g_BeH[4 * 128 * LDA];
__device__ __align__(16) __nv_bfloat16 g_BeL[4 * 128 * LDA];

// ---------------- helpers ----------------
__device__ __forceinline__ void split2(float x0, float x1, unsigned& hi, unsigned& lo) {
    __nv_bfloat162 h = __floats2bfloat162_rn(x0, x1);
    float r0 = x0 - __bfloat162float(h.x);
    float r1 = x1 - __bfloat162float(h.y);
    __nv_bfloat162 l = __floats2bfloat162_rn(r0, r1);
    hi = *(unsigned*)&h;
    lo = *(unsigned*)&l;
}

__device__ __forceinline__ void mma16816(float* d, const unsigned* a, unsigned b0, unsigned b1) {
    asm volatile(
        "mma.sync.aligned.m16n8k16.row.col.f32.bf16.bf16.f32 "
        "{%0,%1,%2,%3}, {%4,%5,%6,%7}, {%8,%9}, {%0,%1,%2,%3};"
        : "+f"(d[0]), "+f"(d[1]), "+f"(d[2]), "+f"(d[3])
        : "r"(a[0]), "r"(a[1]), "r"(a[2]), "r"(a[3]), "r"(b0), "r"(b1));
}
__device__ __forceinline__ void ldsm4(unsigned r[4], unsigned addr) {
    asm volatile("ldmatrix.sync.aligned.m8n8.x4.shared.b16 {%0,%1,%2,%3}, [%4];"
        : "=r"(r[0]), "=r"(r[1]), "=r"(r[2]), "=r"(r[3]) : "r"(addr));
}
__device__ __forceinline__ unsigned scvta(const void* p) {
    return (unsigned)__cvta_generic_to_shared(p);
}

// warp tile m32 x n32. d[2][4][4] accumulators.
// A x4 frag: lane -> row (l&7)+((l>>3)&1)*8, col (l>>4)*8
// B x4 frag: lane -> row (l&7)+(l>>4)*8,     col ((l>>3)&1)*8
__device__ __forceinline__ void gemm_2t(
    const __nv_bfloat16* A1, const __nv_bfloat16* A2, const __nv_bfloat16* B,
    int wm, int wn, int lane, float d[2][4][4])
{
    int ar = (lane & 7) + ((lane >> 3) & 1) * 8;
    int ac = (lane >> 4) * 8;
    int br = (lane & 7) + (lane >> 4) * 8;
    int bc = ((lane >> 3) & 1) * 8;
    unsigned aA1[2], aA2[2], aB[2];
#pragma unroll
    for (int t = 0; t < 2; t++) {
        aA1[t] = scvta(A1 + (wm * 32 + t * 16 + ar) * LDA + ac);
        aA2[t] = scvta(A2 + (wm * 32 + t * 16 + ar) * LDA + ac);
    }
#pragma unroll
    for (int jp = 0; jp < 2; jp++)
        aB[jp] = scvta(B + (wn * 32 + jp * 16 + br) * LDA + bc);

#pragma unroll
    for (int ks = 0; ks < 8; ks++) {
        unsigned ko = ks * 32;
        unsigned a1[2][4], a2[2][4];
#pragma unroll
        for (int t = 0; t < 2; t++) { ldsm4(a1[t], aA1[t] + ko); ldsm4(a2[t], aA2[t] + ko); }
#pragma unroll
        for (int jp = 0; jp < 2; jp++) {
            unsigned bb[4];
            ldsm4(bb, aB[jp] + ko);
#pragma unroll
            for (int t = 0; t < 2; t++) {
                mma16816(d[t][jp * 2 + 0], a1[t], bb[0], bb[1]);
                mma16816(d[t][jp * 2 + 0], a2[t], bb[0], bb[1]);
                mma16816(d[t][jp * 2 + 1], a1[t], bb[2], bb[3]);
                mma16816(d[t][jp * 2 + 1], a2[t], bb[2], bb[3]);
            }
        }
    }
}

__device__ __forceinline__ void gemm_1t(
    const __nv_bfloat16* A1, const __nv_bfloat16* B,
    int wm, int wn, int lane, float d[2][4][4])
{
    int ar = (lane & 7) + ((lane >> 3) & 1) * 8;
    int ac = (lane >> 4) * 8;
    int br = (lane & 7) + (lane >> 4) * 8;
    int bc = ((lane >> 3) & 1) * 8;
    unsigned aA1[2], aB[2];
#pragma unroll
    for (int t = 0; t < 2; t++)
        aA1[t] = scvta(A1 + (wm * 32 + t * 16 + ar) * LDA + ac);
#pragma unroll
    for (int jp = 0; jp < 2; jp++)
        aB[jp] = scvta(B + (wn * 32 + jp * 16 + br) * LDA + bc);

#pragma unroll
    for (int ks = 0; ks < 8; ks++) {
        unsigned ko = ks * 32;
        unsigned a1[2][4];
#pragma unroll
        for (int t = 0; t < 2; t++) ldsm4(a1[t], aA1[t] + ko);
#pragma unroll
        for (int jp = 0; jp < 2; jp++) {
            unsigned bb[4];
            ldsm4(bb, aB[jp] + ko);
#pragma unroll
            for (int t = 0; t < 2; t++) {
                mma16816(d[t][jp * 2 + 0], a1[t], bb[0], bb[1]);
                mma16816(d[t][jp * 2 + 1], a1[t], bb[2], bb[3]);
            }
        }
    }
}

__device__ __forceinline__ void copyB(const __nv_bfloat16* src, __nv_bfloat16* dst, int tid, int nthr) {
    const float4* s = (const float4*)src;
    float4* d = (float4*)dst;
    for (int u = tid; u < 2176; u += nthr) d[u] = s[u];
}

// ---------------------------------------------------------------------------
// prep: fold Q-path through W_k (m-table)
// ---------------------------------------------------------------------------
__global__ void prep_kernel(const float* __restrict__ rel_emb,
                            const float* __restrict__ W_q,
                            const float* __restrict__ b_q,
                            const float* __restrict__ W_k,
                            const float* __restrict__ b_k) {
    __shared__ float qh[128];
    int r = blockIdx.x;
    int c = threadIdx.x;
    float s = b_q[c];
#pragma unroll 16
    for (int t = 0; t < 64; t++) s = fmaf(rel_emb[r * 64 + t], W_q[t * 128 + c], s);
    qh[c] = s;
    __syncthreads();
    int k = threadIdx.x;
    float m[4] = {0.f, 0.f, 0.f, 0.f};
#pragma unroll 8
    for (int d = 0; d < 32; d++)
#pragma unroll
        for (int h = 0; h < 4; h++)
            m[h] = fmaf(W_k[k * 128 + h * 32 + d], qh[h * 32 + d], m[h]);
    float4 m4 = {m[0], m[1], m[2], m[3]};
    *(float4*)(g_M + r * 512 + k * 4) = m4;
    if (k < 4) {
        float cc = 0.f;
#pragma unroll 8
        for (int d = 0; d < 32; d++) cc = fmaf(b_k[k * 32 + d], qh[k * 32 + d], cc);
        g_C[r * 4 + k] = cc;
    }
}

// ---------------------------------------------------------------------------
// packb
// ---------------------------------------------------------------------------
__global__ void packb_kernel(const float* __restrict__ Wv,
                             const float* __restrict__ Wo1,
                             const float* __restrict__ Wedge) {
    int idx = blockIdx.x * 256 + threadIdx.x;
    if (idx < 16384) {
        int n = idx & 127, k = idx >> 7;
        float x = Wv[k * 128 + n];
        __nv_bfloat16 h = __float2bfloat16(x);
        g_BvH[n * LDA + k] = h;
        g_BvL[n * LDA + k] = __float2bfloat16(x - __bfloat162float(h));
    } else if (idx < 32768) {
        int t = idx - 16384;
        int n = t & 127, k = t >> 7;
        float x = Wo1[k * 128 + n];
        __nv_bfloat16 h = __float2bfloat16(x);
        g_BoH[n * LDA + k] = h;
        g_BoL[n * LDA + k] = __float2bfloat16(x - __bfloat162float(h));
    } else if (idx < 98304) {
        int t = idx - 32768;
        int cb = t >> 15;
        int r = t & 32767;
        int k = r >> 7;
        int n = r & 127;
        int chunk = k >> 7, kl = k & 127;
        size_t o = (size_t)((cb * 2 + chunk) * 128 + n) * LDA + kl;
        float x = Wedge[(size_t)(cb * 256 + k) * 128 + n];
        __nv_bfloat16 h = __float2bfloat16(x);
        g_BeH[o] = h;
        g_BeL[o] = __float2bfloat16(x - __bfloat162float(h));
    }
}

// ---------------------------------------------------------------------------
// nodeproj: 512 threads, 16 warps m32n32, spill-free
// ---------------------------------------------------------------------------
__global__ __launch_bounds__(512) void nodeproj_kernel(const float* __restrict__ emb,
                                                       int n_nodes) {
    extern __shared__ __align__(16) char sm[];
    __nv_bfloat16* AH = (__nv_bfloat16*)sm;
    __nv_bfloat16* AL = AH + 128 * LDA;
    __nv_bfloat16* B  = AL + 128 * LDA;

    int tid = threadIdx.x;
    int lane = tid & 31, wid = tid >> 5;
    int g = lane >> 2, tk = lane & 3;
    int wm = wid >> 2, wn = wid & 3;
    int n0 = blockIdx.x * 128;
    int cb = blockIdx.y;

    float d[2][4][4];
#pragma unroll
    for (int t = 0; t < 2; t++)
#pragma unroll
        for (int j = 0; j < 4; j++)
#pragma unroll
            for (int c = 0; c < 4; c++) d[t][j][c] = 0.f;

    for (int chunk = 0; chunk < 2; chunk++) {
        __syncthreads();
        // build A chunk: 4 threads per row, 8 float4 each
        {
            int row = tid >> 2, q = tid & 3;
            int n = n0 + row; if (n >= n_nodes) n = n_nodes - 1;
            const float4* np = (const float4*)(emb + (size_t)n * EMB + chunk * 128);
#pragma unroll
            for (int u = 0; u < 8; u++) {
                int idx = q + u * 4;
                float4 v = np[idx];
                unsigned h0, l0, h1, l1;
                split2(v.x, v.y, h0, l0);
                split2(v.z, v.w, h1, l1);
                int c = idx * 4;
                *(unsigned*)(AH + row * LDA + c) = h0;
                *(unsigned*)(AH + row * LDA + c + 2) = h1;
                *(unsigned*)(AL + row * LDA + c) = l0;
                *(unsigned*)(AL + row * LDA + c + 2) = l1;
            }
        }
        copyB(g_BeH + (size_t)(cb * 2 + chunk) * 128 * LDA, B, tid, 512);
        __syncthreads();
        gemm_2t(AH, AL, B, wm, wn, lane, d);
        __syncthreads();
        copyB(g_BeL + (size_t)(cb * 2 + chunk) * 128 * LDA, B, tid, 512);
        __syncthreads();
        gemm_1t(AH, B, wm, wn, lane, d);
    }
#pragma unroll
    for (int t = 0; t < 2; t++) {
        int lr = wm * 32 + t * 16 + g;
#pragma unroll
        for (int j = 0; j < 4; j++) {
            int col = cb * 128 + wn * 32 + j * 8 + 2 * tk;
            int n = n0 + lr;
            if (n < n_nodes) {
                float2 v = {d[t][j][0], d[t][j][1]};
                *(float2*)(g_P + (size_t)n * 256 + col) = v;
            }
            int n2 = n0 + lr + 8;
            if (n2 < n_nodes) {
                float2 v = {d[t][j][2], d[t][j][3]};
                *(float2*)(g_P + (size_t)n2 * 256 + col) = v;
            }
        }
    }
}

// ---------------------------------------------------------------------------
// edge kernel: 512 threads, 16 warps m32n32, spill-free
// layout: AH 0, AL 34816, B 69632, sSc 104448(2048), sSrc 106496, sTgt 107008,
//         sRel 107520, sBv 108032, sBo 108544, sW2 109056, sOut 109568(2048)
// total 111616
// ---------------------------------------------------------------------------
__global__ __launch_bounds__(512) void edge_kernel(
    const int* __restrict__ edge_index, const int* __restrict__ rel_type,
    const float* __restrict__ b_edge,
    const float* __restrict__ b_v, const float* __restrict__ b_o1,
    const float* __restrict__ W_o2, const float* __restrict__ b_o2,
    float* __restrict__ out, int E) {
    extern __shared__ __align__(16) char sm[];
    __nv_bfloat16* AH = (__nv_bfloat16*)sm;
    __nv_bfloat16* AL = AH + 128 * LDA;
    __nv_bfloat16* B  = AL + 128 * LDA;
    float* sSc = (float*)(sm + 104448);
    int* sSrc  = (int*)(sm + 106496);
    int* sTgt  = (int*)(sm + 107008);
    int* sRel  = (int*)(sm + 107520);
    float* sBv = (float*)(sm + 108032);
    float* sBo = (float*)(sm + 108544);
    float* sW2 = (float*)(sm + 109056);
    float* sOut = (float*)(sm + 109568);

    int tid = threadIdx.x;
    int lane = tid & 31, wid = tid >> 5;
    int g = lane >> 2, tk = lane & 3;
    int wm = wid >> 2, wn = wid & 3;
    int e0 = blockIdx.x * 128;

    if (tid < 128) {
        int e = e0 + tid;
        int eg = e < E ? e : E - 1;
        sSrc[tid] = edge_index[eg];
        sTgt[tid] = edge_index[E + eg];
        sRel[tid] = rel_type[eg];
        sBv[tid] = b_v[tid];
        sBo[tid] = b_o1[tid];
        sW2[tid] = W_o2[tid];
    }
    copyB(g_BvH, B, tid, 512);
    __syncthreads();

    // build hs = relu(P[src][0:128] + P[tgt][128:256] + b_edge), split; 4 thr/row
    {
        int row = tid >> 2, q = tid & 3;
        const float4* ps = (const float4*)(g_P + (size_t)sSrc[row] * 256);
        const float4* pt = (const float4*)(g_P + (size_t)sTgt[row] * 256 + 128);
        const float4* bb = (const float4*)b_edge;
#pragma unroll
        for (int u = 0; u < 8; u++) {
            int idx = q + u * 4;
            float4 a = ps[idx], b = pt[idx], c = bb[idx];
            float x0 = fmaxf(a.x + b.x + c.x, 0.f);
            float x1 = fmaxf(a.y + b.y + c.y, 0.f);
            float x2 = fmaxf(a.z + b.z + c.z, 0.f);
            float x3 = fmaxf(a.w + b.w + c.w, 0.f);
            unsigned h0, l0, h1, l1;
            split2(x0, x1, h0, l0);
            split2(x2, x3, h1, l1);
            int cc = idx * 4;
            *(unsigned*)(AH + row * LDA + cc) = h0;
            *(unsigned*)(AH + row * LDA + cc + 2) = h1;
            *(unsigned*)(AL + row * LDA + cc) = l0;
            *(unsigned*)(AL + row * LDA + cc + 2) = l1;
        }
    }
    __syncthreads();

    // scores: 32 ty-groups x 4 edges
    {
        int tx = tid & 15, ty = tid >> 4;
#pragma unroll
        for (int i = 0; i < 4; i++) {
            int e = ty * 4 + i;
            int r = sRel[e];
            const float4* gm = (const float4*)(g_M + r * 512);
            float p[4] = {0.f, 0.f, 0.f, 0.f};
#pragma unroll
            for (int j = 0; j < 4; j++) {
                int k = j * 32 + 2 * tx;
                float2 xh = __bfloat1622float2(*(const __nv_bfloat162*)(AH + e * LDA + k));
                float2 xl = __bfloat1622float2(*(const __nv_bfloat162*)(AL + e * LDA + k));
                float h0 = xh.x + xl.x, h1 = xh.y + xl.y;
                float4 m0 = __ldg(gm + k);
                float4 m1 = __ldg(gm + k + 1);
                p[0] += h0 * m0.x + h1 * m1.x;
                p[1] += h0 * m0.y + h1 * m1.y;
                p[2] += h0 * m0.z + h1 * m1.z;
                p[3] += h0 * m0.w + h1 * m1.w;
            }
#pragma unroll
            for (int m = 1; m < 16; m <<= 1)
#pragma unroll
                for (int j = 0; j < 4; j++) p[j] += __shfl_xor_sync(0xffffffffu, p[j], m);
            if (tx == 0) {
#pragma unroll
                for (int j = 0; j < 4; j++)
                    sSc[e * 4 + j] = (p[j] + __ldg(g_C + r * 4 + j)) * 0.17677669529663687f;
            }
        }
    }

    // GEMM1: Ah*BvH + Al*BvH ; then Ah*BvL
    float d[2][4][4];
#pragma unroll
    for (int t = 0; t < 2; t++)
#pragma unroll
        for (int j = 0; j < 4; j++)
#pragma unroll
            for (int c = 0; c < 4; c++) d[t][j][c] = 0.f;
    gemm_2t(AH, AL, B, wm, wn, lane, d);
    __syncthreads();
    copyB(g_BvL, B, tid, 512);
    __syncthreads();
    gemm_1t(AH, B, wm, wn, lane, d);
    __syncthreads();

    // epilogue1: softmax over heads; warp's 32 cols = head wn only.
    // hs += attn[wn]*(V + b_v), re-split in place (bf16x2 vectorized)
#pragma unroll
    for (int t = 0; t < 2; t++) {
#pragma unroll
        for (int ch = 0; ch < 2; ch++) {
            int row = wm * 32 + t * 16 + g + ch * 8;
            float s0 = sSc[row * 4 + 0], s1 = sSc[row * 4 + 1];
            float s2 = sSc[row * 4 + 2], s3 = sSc[row * 4 + 3];
            float mx = fmaxf(fmaxf(s0, s1), fmaxf(s2, s3));
            float x0 = __expf(s0 - mx), x1 = __expf(s1 - mx);
            float x2 = __expf(s2 - mx), x3 = __expf(s3 - mx);
            float inv = 1.f / (x0 + x1 + x2 + x3);
            float aw = (wn == 0 ? x0 : wn == 1 ? x1 : wn == 2 ? x2 : x3) * inv;
#pragma unroll
            for (int j = 0; j < 4; j++) {
                int col = wn * 32 + j * 8 + 2 * tk;
                float2 xh = __bfloat1622float2(*(__nv_bfloat162*)(AH + row * LDA + col));
                float2 xl = __bfloat1622float2(*(__nv_bfloat162*)(AL + row * LDA + col));
                float v0 = d[t][j][ch * 2 + 0] + sBv[col];
                float v1 = d[t][j][ch * 2 + 1] + sBv[col + 1];
                float n0 = (xh.x + xl.x) + aw * v0;
                float n1 = (xh.y + xl.y) + aw * v1;
                unsigned hh, ll;
                split2(n0, n1, hh, ll);
                *(unsigned*)(AH + row * LDA + col) = hh;
                *(unsigned*)(AL + row * LDA + col) = ll;
            }
        }
    }
    copyB(g_BoH, B, tid, 512);
    __syncthreads();

    // GEMM2
#pragma unroll
    for (int t = 0; t < 2; t++)
#pragma unroll
        for (int j = 0; j < 4; j++)
#pragma unroll
            for (int c = 0; c < 4; c++) d[t][j][c] = 0.f;
    gemm_2t(AH, AL, B, wm, wn, lane, d);
    __syncthreads();
    copyB(g_BoL, B, tid, 512);
    __syncthreads();
    gemm_1t(AH, B, wm, wn, lane, d);

    // epilogue2: relu(D2 + b_o1) . W_o2 partial, quad reduce, per-wn partials
    float pacc[2][2] = {{0.f, 0.f}, {0.f, 0.f}};
#pragma unroll
    for (int t = 0; t < 2; t++)
#pragma unroll
        for (int ch = 0; ch < 2; ch++)
#pragma unroll
            for (int j = 0; j < 4; j++)
#pragma unroll
                for (int cb2 = 0; cb2 < 2; cb2++) {
                    int col = wn * 32 + j * 8 + 2 * tk + cb2;
                    float h = fmaxf(d[t][j][ch * 2 + cb2] + sBo[col], 0.f);
                    pacc[t][ch] = fmaf(h, sW2[col], pacc[t][ch]);
                }
#pragma unroll
    for (int m = 1; m <= 2; m <<= 1)
#pragma unroll
        for (int t = 0; t < 2; t++)
#pragma unroll
            for (int ch = 0; ch < 2; ch++)
                pacc[t][ch] += __shfl_xor_sync(0xffffffffu, pacc[t][ch], m);
    if (tk == 0) {
#pragma unroll
        for (int t = 0; t < 2; t++)
#pragma unroll
            for (int ch = 0; ch < 2; ch++) {
                int row = wm * 32 + t * 16 + g + ch * 8;
                sOut[wn * 128 + row] = pacc[t][ch];
            }
    }
    __syncthreads();
    if (tid < 128) {
        int e = e0 + tid;
        if (e < E)
            out[e] = sOut[tid] + sOut[128 + tid] + sOut[256 + tid] + sOut[384 + tid] + __ldg(b_o2);
    }
}

// ---------------------------------------------------------------------------
extern "C" void kernel_launch(void* const* d_in, const int* in_sizes, int n_in,
                              void* d_out, int out_size) {
    const float* node_emb = (const float*)d_in[0];
    const int*   edge_index = (const int*)d_in[1];
    const int*   rel_type = (const int*)d_in[2];
    const float* rel_emb = (const float*)d_in[3];
    const float* W_edge = (const float*)d_in[4];
    const float* b_edge = (const float*)d_in[5];
    const float* W_q = (const float*)d_in[6];
    const float* b_q = (const float*)d_in[7];
    const float* W_k = (const float*)d_in[8];
    const float* b_k = (const float*)d_in[9];
    const float* W_v = (const float*)d_in[10];
    const float* b_v = (const float*)d_in[11];
    const float* W_o1 = (const float*)d_in[12];
    const float* b_o1 = (const float*)d_in[13];
    const float* W_o2 = (const float*)d_in[14];
    const float* b_o2 = (const float*)d_in[15];
    float* out = (float*)d_out;

    int n_nodes = in_sizes[0] / EMB;   // 100000
    int E = in_sizes[2];               // 500000

    prep_kernel<<<N_REL, 128>>>(rel_emb, W_q, b_q, W_k, b_k);
    packb_kernel<<<384, 256>>>(W_v, W_o1, W_edge);

    const int SMEM_NP = 3 * 128 * LDA * 2;     // 104448
    cudaFuncSetAttribute(nodeproj_kernel, cudaFuncAttributeMaxDynamicSharedMemorySize, SMEM_NP);
    dim3 g2((n_nodes + 127) / 128, 2);
    nodeproj_kernel<<<g2, 512, SMEM_NP>>>(node_emb, n_nodes);

    const int SMEM_E = 111616;
    cudaFuncSetAttribute(edge_kernel, cudaFuncAttributeMaxDynamicSharedMemorySize, SMEM_E);
    edge_kernel<<<(E + 127) / 128, 512, SMEM_E>>>(
        edge_index, rel_type, b_edge, b_v, b_o1, W_o2, b_o2, out, E);
}

// round 9
// speedup vs baseline: 1.4717x; 1.2430x over previous
#include <cuda_runtime.h>
#include <cuda_bf16.h>
#include <cstddef>

#define EMB 256
#define HID 128
#define N_REL 10
#define LDA 136   // padded bf16 row stride (272B: rows step 4 banks -> LDSM conflict-free)

// ---------------- global scratch ----------------
__device__ float g_P[(size_t)100000 * 256];   // per-node projections
__device__ float g_M[N_REL * 128 * 4];        // folded K/Q table m[r][k][h]
__device__ float g_C[N_REL * 4];              // folded bias c[r][h]
__device__ __align__(16) __nv_bfloat16 g_BvH[128 * LDA];
__device__ __align__(16) __nv_bfloat16 g_BvL[128 * LDA];
__device__ __align__(16) __nv_bfloat16 g_BoH[128 * LDA];
__device__ __align__(16) __nv_bfloat16 g_BoL[128 * LDA];
__device__ __align__(16) __nv_bfloat16 g_BeH[4 * 128 * LDA];
__device__ __align__(16) __nv_bfloat16 g_BeL[4 * 128 * LDA];

// ---------------- helpers ----------------
__device__ __forceinline__ void split2(float x0, float x1, unsigned& hi, unsigned& lo) {
    __nv_bfloat162 h = __floats2bfloat162_rn(x0, x1);
    float r0 = x0 - __bfloat162float(h.x);
    float r1 = x1 - __bfloat162float(h.y);
    __nv_bfloat162 l = __floats2bfloat162_rn(r0, r1);
    hi = *(unsigned*)&h;
    lo = *(unsigned*)&l;
}

__device__ __forceinline__ void mma16816(float* d, const unsigned* a, unsigned b0, unsigned b1) {
    asm volatile(
        "mma.sync.aligned.m16n8k16.row.col.f32.bf16.bf16.f32 "
        "{%0,%1,%2,%3}, {%4,%5,%6,%7}, {%8,%9}, {%0,%1,%2,%3};"
        : "+f"(d[0]), "+f"(d[1]), "+f"(d[2]), "+f"(d[3])
        : "r"(a[0]), "r"(a[1]), "r"(a[2]), "r"(a[3]), "r"(b0), "r"(b1));
}
__device__ __forceinline__ void ldsm4(unsigned r[4], unsigned addr) {
    asm volatile("ldmatrix.sync.aligned.m8n8.x4.shared.b16 {%0,%1,%2,%3}, [%4];"
        : "=r"(r[0]), "=r"(r[1]), "=r"(r[2]), "=r"(r[3]) : "r"(addr));
}
__device__ __forceinline__ unsigned scvta(const void* p) {
    return (unsigned)__cvta_generic_to_shared(p);
}

// warp tile m32 x n32. d[2][4][4] accumulators.
__device__ __forceinline__ void gemm_2t(
    const __nv_bfloat16* A1, const __nv_bfloat16* A2, const __nv_bfloat16* B,
    int wm, int wn, int lane, float d[2][4][4])
{
    int ar = (lane & 7) + ((lane >> 3) & 1) * 8;
    int ac = (lane >> 4) * 8;
    int br = (lane & 7) + (lane >> 4) * 8;
    int bc = ((lane >> 3) & 1) * 8;
    unsigned aA1[2], aA2[2], aB[2];
#pragma unroll
    for (int t = 0; t < 2; t++) {
        aA1[t] = scvta(A1 + (wm * 32 + t * 16 + ar) * LDA + ac);
        aA2[t] = scvta(A2 + (wm * 32 + t * 16 + ar) * LDA + ac);
    }
#pragma unroll
    for (int jp = 0; jp < 2; jp++)
        aB[jp] = scvta(B + (wn * 32 + jp * 16 + br) * LDA + bc);

#pragma unroll
    for (int ks = 0; ks < 8; ks++) {
        unsigned ko = ks * 32;
        unsigned a1[2][4], a2[2][4];
#pragma unroll
        for (int t = 0; t < 2; t++) { ldsm4(a1[t], aA1[t] + ko); ldsm4(a2[t], aA2[t] + ko); }
#pragma unroll
        for (int jp = 0; jp < 2; jp++) {
            unsigned bb[4];
            ldsm4(bb, aB[jp] + ko);
#pragma unroll
            for (int t = 0; t < 2; t++) {
                mma16816(d[t][jp * 2 + 0], a1[t], bb[0], bb[1]);
                mma16816(d[t][jp * 2 + 0], a2[t], bb[0], bb[1]);
                mma16816(d[t][jp * 2 + 1], a1[t], bb[2], bb[3]);
                mma16816(d[t][jp * 2 + 1], a2[t], bb[2], bb[3]);
            }
        }
    }
}

__device__ __forceinline__ void gemm_1t(
    const __nv_bfloat16* A1, const __nv_bfloat16* B,
    int wm, int wn, int lane, float d[2][4][4])
{
    int ar = (lane & 7) + ((lane >> 3) & 1) * 8;
    int ac = (lane >> 4) * 8;
    int br = (lane & 7) + (lane >> 4) * 8;
    int bc = ((lane >> 3) & 1) * 8;
    unsigned aA1[2], aB[2];
#pragma unroll
    for (int t = 0; t < 2; t++)
        aA1[t] = scvta(A1 + (wm * 32 + t * 16 + ar) * LDA + ac);
#pragma unroll
    for (int jp = 0; jp < 2; jp++)
        aB[jp] = scvta(B + (wn * 32 + jp * 16 + br) * LDA + bc);

#pragma unroll
    for (int ks = 0; ks < 8; ks++) {
        unsigned ko = ks * 32;
        unsigned a1[2][4];
#pragma unroll
        for (int t = 0; t < 2; t++) ldsm4(a1[t], aA1[t] + ko);
#pragma unroll
        for (int jp = 0; jp < 2; jp++) {
            unsigned bb[4];
            ldsm4(bb, aB[jp] + ko);
#pragma unroll
            for (int t = 0; t < 2; t++) {
                mma16816(d[t][jp * 2 + 0], a1[t], bb[0], bb[1]);
                mma16816(d[t][jp * 2 + 1], a1[t], bb[2], bb[3]);
            }
        }
    }
}

__device__ __forceinline__ void copyB(const __nv_bfloat16* src, __nv_bfloat16* dst, int tid, int nthr) {
    const float4* s = (const float4*)src;
    float4* d = (float4*)dst;
    for (int u = tid; u < 2176; u += nthr) d[u] = s[u];
}

// ---------------------------------------------------------------------------
// prep: fold Q-path through W_k (m-table)
// ---------------------------------------------------------------------------
__global__ void prep_kernel(const float* __restrict__ rel_emb,
                            const float* __restrict__ W_q,
                            const float* __restrict__ b_q,
                            const float* __restrict__ W_k,
                            const float* __restrict__ b_k) {
    __shared__ float qh[128];
    int r = blockIdx.x;
    int c = threadIdx.x;
    float s = b_q[c];
#pragma unroll 16
    for (int t = 0; t < 64; t++) s = fmaf(rel_emb[r * 64 + t], W_q[t * 128 + c], s);
    qh[c] = s;
    __syncthreads();
    int k = threadIdx.x;
    float m[4] = {0.f, 0.f, 0.f, 0.f};
#pragma unroll 8
    for (int d = 0; d < 32; d++)
#pragma unroll
        for (int h = 0; h < 4; h++)
            m[h] = fmaf(W_k[k * 128 + h * 32 + d], qh[h * 32 + d], m[h]);
    float4 m4 = {m[0], m[1], m[2], m[3]};
    *(float4*)(g_M + r * 512 + k * 4) = m4;
    if (k < 4) {
        float cc = 0.f;
#pragma unroll 8
        for (int d = 0; d < 32; d++) cc = fmaf(b_k[k * 32 + d], qh[k * 32 + d], cc);
        g_C[r * 4 + k] = cc;
    }
}

// ---------------------------------------------------------------------------
// packb
// ---------------------------------------------------------------------------
__global__ void packb_kernel(const float* __restrict__ Wv,
                             const float* __restrict__ Wo1,
                             const float* __restrict__ Wedge) {
    int idx = blockIdx.x * 256 + threadIdx.x;
    if (idx < 16384) {
        int n = idx & 127, k = idx >> 7;
        float x = Wv[k * 128 + n];
        __nv_bfloat16 h = __float2bfloat16(x);
        g_BvH[n * LDA + k] = h;
        g_BvL[n * LDA + k] = __float2bfloat16(x - __bfloat162float(h));
    } else if (idx < 32768) {
        int t = idx - 16384;
        int n = t & 127, k = t >> 7;
        float x = Wo1[k * 128 + n];
        __nv_bfloat16 h = __float2bfloat16(x);
        g_BoH[n * LDA + k] = h;
        g_BoL[n * LDA + k] = __float2bfloat16(x - __bfloat162float(h));
    } else if (idx < 98304) {
        int t = idx - 32768;
        int cb = t >> 15;
        int r = t & 32767;
        int k = r >> 7;
        int n = r & 127;
        int chunk = k >> 7, kl = k & 127;
        size_t o = (size_t)((cb * 2 + chunk) * 128 + n) * LDA + kl;
        float x = Wedge[(size_t)(cb * 256 + k) * 128 + n];
        __nv_bfloat16 h = __float2bfloat16(x);
        g_BeH[o] = h;
        g_BeL[o] = __float2bfloat16(x - __bfloat162float(h));
    }
}

// ---------------------------------------------------------------------------
// nodeproj: 512 threads, 16 warps m32n32, 2 blocks/SM
// ---------------------------------------------------------------------------
__global__ __launch_bounds__(512, 2) void nodeproj_kernel(const float* __restrict__ emb,
                                                          int n_nodes) {
    extern __shared__ __align__(16) char sm[];
    __nv_bfloat16* AH = (__nv_bfloat16*)sm;
    __nv_bfloat16* AL = AH + 128 * LDA;
    __nv_bfloat16* B  = AL + 128 * LDA;

    int tid = threadIdx.x;
    int lane = tid & 31, wid = tid >> 5;
    int g = lane >> 2, tk = lane & 3;
    int wm = wid >> 2, wn = wid & 3;
    int n0 = blockIdx.x * 128;
    int cb = blockIdx.y;

    float d[2][4][4];
#pragma unroll
    for (int t = 0; t < 2; t++)
#pragma unroll
        for (int j = 0; j < 4; j++)
#pragma unroll
            for (int c = 0; c < 4; c++) d[t][j][c] = 0.f;

    for (int chunk = 0; chunk < 2; chunk++) {
        __syncthreads();
        {
            int row = tid >> 2, q = tid & 3;
            int n = n0 + row; if (n >= n_nodes) n = n_nodes - 1;
            const float4* np = (const float4*)(emb + (size_t)n * EMB + chunk * 128);
#pragma unroll
            for (int u = 0; u < 8; u++) {
                int idx = q + u * 4;
                float4 v = np[idx];
                unsigned h0, l0, h1, l1;
                split2(v.x, v.y, h0, l0);
                split2(v.z, v.w, h1, l1);
                int c = idx * 4;
                *(unsigned*)(AH + row * LDA + c) = h0;
                *(unsigned*)(AH + row * LDA + c + 2) = h1;
                *(unsigned*)(AL + row * LDA + c) = l0;
                *(unsigned*)(AL + row * LDA + c + 2) = l1;
            }
        }
        copyB(g_BeH + (size_t)(cb * 2 + chunk) * 128 * LDA, B, tid, 512);
        __syncthreads();
        gemm_2t(AH, AL, B, wm, wn, lane, d);
        __syncthreads();
        copyB(g_BeL + (size_t)(cb * 2 + chunk) * 128 * LDA, B, tid, 512);
        __syncthreads();
        gemm_1t(AH, B, wm, wn, lane, d);
    }
#pragma unroll
    for (int t = 0; t < 2; t++) {
        int lr = wm * 32 + t * 16 + g;
#pragma unroll
        for (int j = 0; j < 4; j++) {
            int col = cb * 128 + wn * 32 + j * 8 + 2 * tk;
            int n = n0 + lr;
            if (n < n_nodes) {
                float2 v = {d[t][j][0], d[t][j][1]};
                *(float2*)(g_P + (size_t)n * 256 + col) = v;
            }
            int n2 = n0 + lr + 8;
            if (n2 < n_nodes) {
                float2 v = {d[t][j][2], d[t][j][3]};
                *(float2*)(g_P + (size_t)n2 * 256 + col) = v;
            }
        }
    }
}

// ---------------------------------------------------------------------------
// edge kernel: 512 threads, 16 warps m32n32, 2 blocks/SM
// ---------------------------------------------------------------------------
__global__ __launch_bounds__(512, 2) void edge_kernel(
    const int* __restrict__ edge_index, const int* __restrict__ rel_type,
    const float* __restrict__ b_edge,
    const float* __restrict__ b_v, const float* __restrict__ b_o1,
    const float* __restrict__ W_o2, const float* __restrict__ b_o2,
    float* __restrict__ out, int E) {
    extern __shared__ __align__(16) char sm[];
    __nv_bfloat16* AH = (__nv_bfloat16*)sm;
    __nv_bfloat16* AL = AH + 128 * LDA;
    __nv_bfloat16* B  = AL + 128 * LDA;
    float* sSc = (float*)(sm + 104448);
    int* sSrc  = (int*)(sm + 106496);
    int* sTgt  = (int*)(sm + 107008);
    int* sRel  = (int*)(sm + 107520);
    float* sBv = (float*)(sm + 108032);
    float* sBo = (float*)(sm + 108544);
    float* sW2 = (float*)(sm + 109056);
    float* sOut = (float*)(sm + 109568);

    int tid = threadIdx.x;
    int lane = tid & 31, wid = tid >> 5;
    int g = lane >> 2, tk = lane & 3;
    int wm = wid >> 2, wn = wid & 3;
    int e0 = blockIdx.x * 128;

    if (tid < 128) {
        int e = e0 + tid;
        int eg = e < E ? e : E - 1;
        sSrc[tid] = edge_index[eg];
        sTgt[tid] = edge_index[E + eg];
        sRel[tid] = rel_type[eg];
        sBv[tid] = b_v[tid];
        sBo[tid] = b_o1[tid];
        sW2[tid] = W_o2[tid];
    }
    copyB(g_BvH, B, tid, 512);
    __syncthreads();

    // build hs, split; 4 thr/row
    {
        int row = tid >> 2, q = tid & 3;
        const float4* ps = (const float4*)(g_P + (size_t)sSrc[row] * 256);
        const float4* pt = (const float4*)(g_P + (size_t)sTgt[row] * 256 + 128);
        const float4* bb = (const float4*)b_edge;
#pragma unroll
        for (int u = 0; u < 8; u++) {
            int idx = q + u * 4;
            float4 a = ps[idx], b = pt[idx], c = bb[idx];
            float x0 = fmaxf(a.x + b.x + c.x, 0.f);
            float x1 = fmaxf(a.y + b.y + c.y, 0.f);
            float x2 = fmaxf(a.z + b.z + c.z, 0.f);
            float x3 = fmaxf(a.w + b.w + c.w, 0.f);
            unsigned h0, l0, h1, l1;
            split2(x0, x1, h0, l0);
            split2(x2, x3, h1, l1);
            int cc = idx * 4;
            *(unsigned*)(AH + row * LDA + cc) = h0;
            *(unsigned*)(AH + row * LDA + cc + 2) = h1;
            *(unsigned*)(AL + row * LDA + cc) = l0;
            *(unsigned*)(AL + row * LDA + cc + 2) = l1;
        }
    }
    __syncthreads();

    // scores
    {
        int tx = tid & 15, ty = tid >> 4;
#pragma unroll
        for (int i = 0; i < 4; i++) {
            int e = ty * 4 + i;
            int r = sRel[e];
            const float4* gm = (const float4*)(g_M + r * 512);
            float p[4] = {0.f, 0.f, 0.f, 0.f};
#pragma unroll
            for (int j = 0; j < 4; j++) {
                int k = j * 32 + 2 * tx;
                float2 xh = __bfloat1622float2(*(const __nv_bfloat162*)(AH + e * LDA + k));
                float2 xl = __bfloat1622float2(*(const __nv_bfloat162*)(AL + e * LDA + k));
                float h0 = xh.x + xl.x, h1 = xh.y + xl.y;
                float4 m0 = __ldg(gm + k);
                float4 m1 = __ldg(gm + k + 1);
                p[0] += h0 * m0.x + h1 * m1.x;
                p[1] += h0 * m0.y + h1 * m1.y;
                p[2] += h0 * m0.z + h1 * m1.z;
                p[3] += h0 * m0.w + h1 * m1.w;
            }
#pragma unroll
            for (int m = 1; m < 16; m <<= 1)
#pragma unroll
                for (int j = 0; j < 4; j++) p[j] += __shfl_xor_sync(0xffffffffu, p[j], m);
            if (tx == 0) {
#pragma unroll
                for (int j = 0; j < 4; j++)
                    sSc[e * 4 + j] = (p[j] + __ldg(g_C + r * 4 + j)) * 0.17677669529663687f;
            }
        }
    }

    // GEMM1
    float d[2][4][4];
#pragma unroll
    for (int t = 0; t < 2; t++)
#pragma unroll
        for (int j = 0; j < 4; j++)
#pragma unroll
            for (int c = 0; c < 4; c++) d[t][j][c] = 0.f;
    gemm_2t(AH, AL, B, wm, wn, lane, d);
    __syncthreads();
    copyB(g_BvL, B, tid, 512);
    __syncthreads();
    gemm_1t(AH, B, wm, wn, lane, d);
    __syncthreads();

    // epilogue1
#pragma unroll
    for (int t = 0; t < 2; t++) {
#pragma unroll
        for (int ch = 0; ch < 2; ch++) {
            int row = wm * 32 + t * 16 + g + ch * 8;
            float s0 = sSc[row * 4 + 0], s1 = sSc[row * 4 + 1];
            float s2 = sSc[row * 4 + 2], s3 = sSc[row * 4 + 3];
            float mx = fmaxf(fmaxf(s0, s1), fmaxf(s2, s3));
            float x0 = __expf(s0 - mx), x1 = __expf(s1 - mx);
            float x2 = __expf(s2 - mx), x3 = __expf(s3 - mx);
            float inv = 1.f / (x0 + x1 + x2 + x3);
            float aw = (wn == 0 ? x0 : wn == 1 ? x1 : wn == 2 ? x2 : x3) * inv;
#pragma unroll
            for (int j = 0; j < 4; j++) {
                int col = wn * 32 + j * 8 + 2 * tk;
                float2 xh = __bfloat1622float2(*(__nv_bfloat162*)(AH + row * LDA + col));
                float2 xl = __bfloat1622float2(*(__nv_bfloat162*)(AL + row * LDA + col));
                float v0 = d[t][j][ch * 2 + 0] + sBv[col];
                float v1 = d[t][j][ch * 2 + 1] + sBv[col + 1];
                float n0 = (xh.x + xl.x) + aw * v0;
                float n1 = (xh.y + xl.y) + aw * v1;
                unsigned hh, ll;
                split2(n0, n1, hh, ll);
                *(unsigned*)(AH + row * LDA + col) = hh;
                *(unsigned*)(AL + row * LDA + col) = ll;
            }
        }
    }
    copyB(g_BoH, B, tid, 512);
    __syncthreads();

    // GEMM2
#pragma unroll
    for (int t = 0; t < 2; t++)
#pragma unroll
        for (int j = 0; j < 4; j++)
#pragma unroll
            for (int c = 0; c < 4; c++) d[t][j][c] = 0.f;
    gemm_2t(AH, AL, B, wm, wn, lane, d);
    __syncthreads();
    copyB(g_BoL, B, tid, 512);
    __syncthreads();
    gemm_1t(AH, B, wm, wn, lane, d);

    // epilogue2
    float pacc[2][2] = {{0.f, 0.f}, {0.f, 0.f}};
#pragma unroll
    for (int t = 0; t < 2; t++)
#pragma unroll
        for (int ch = 0; ch < 2; ch++)
#pragma unroll
            for (int j = 0; j < 4; j++)
#pragma unroll
                for (int cb2 = 0; cb2 < 2; cb2++) {
                    int col = wn * 32 + j * 8 + 2 * tk + cb2;
                    float h = fmaxf(d[t][j][ch * 2 + cb2] + sBo[col], 0.f);
                    pacc[t][ch] = fmaf(h, sW2[col], pacc[t][ch]);
                }
#pragma unroll
    for (int m = 1; m <= 2; m <<= 1)
#pragma unroll
        for (int t = 0; t < 2; t++)
#pragma unroll
            for (int ch = 0; ch < 2; ch++)
                pacc[t][ch] += __shfl_xor_sync(0xffffffffu, pacc[t][ch], m);
    if (tk == 0) {
#pragma unroll
        for (int t = 0; t < 2; t++)
#pragma unroll
            for (int ch = 0; ch < 2; ch++) {
                int row = wm * 32 + t * 16 + g + ch * 8;
                sOut[wn * 128 + row] = pacc[t][ch];
            }
    }
    __syncthreads();
    if (tid < 128) {
        int e = e0 + tid;
        if (e < E)
            out[e] = sOut[tid] + sOut[128 + tid] + sOut[256 + tid] + sOut[384 + tid] + __ldg(b_o2);
    }
}

// ---------------------------------------------------------------------------
extern "C" void kernel_launch(void* const* d_in, const int* in_sizes, int n_in,
                              void* d_out, int out_size) {
    const float* node_emb = (const float*)d_in[0];
    const int*   edge_index = (const int*)d_in[1];
    const int*   rel_type = (const int*)d_in[2];
    const float* rel_emb = (const float*)d_in[3];
    const float* W_edge = (const float*)d_in[4];
    const float* b_edge = (const float*)d_in[5];
    const float* W_q = (const float*)d_in[6];
    const float* b_q = (const float*)d_in[7];
    const float* W_k = (const float*)d_in[8];
    const float* b_k = (const float*)d_in[9];
    const float* W_v = (const float*)d_in[10];
    const float* b_v = (const float*)d_in[11];
    const float* W_o1 = (const float*)d_in[12];
    const float* b_o1 = (const float*)d_in[13];
    const float* W_o2 = (const float*)d_in[14];
    const float* b_o2 = (const float*)d_in[15];
    float* out = (float*)d_out;

    int n_nodes = in_sizes[0] / EMB;   // 100000
    int E = in_sizes[2];               // 500000

    prep_kernel<<<N_REL, 128>>>(rel_emb, W_q, b_q, W_k, b_k);
    packb_kernel<<<384, 256>>>(W_v, W_o1, W_edge);

    const int SMEM_NP = 3 * 128 * LDA * 2;     // 104448
    cudaFuncSetAttribute(nodeproj_kernel, cudaFuncAttributeMaxDynamicSharedMemorySize, SMEM_NP);
    dim3 g2((n_nodes + 127) / 128, 2);
    nodeproj_kernel<<<g2, 512, SMEM_NP>>>(node_emb, n_nodes);

    const int SMEM_E = 111616;
    cudaFuncSetAttribute(edge_kernel, cudaFuncAttributeMaxDynamicSharedMemorySize, SMEM_E);
    edge_kernel<<<(E + 127) / 128, 512, SMEM_E>>>(
        edge_index, rel_type, b_edge, b_v, b_o1, W_o2, b_o2, out, E);
}